// round 9
// baseline (speedup 1.0000x reference)
#include <cuda_runtime.h>
#include <cuda_fp16.h>
#include <math.h>
#include <stdint.h>

// ============================================================================
// ConvolutionKAN as mma.sync fp16 GEMM (sm_100-safe, fp32 accumulate):
//   out[61504,128] = A[61504,2592] @ W[2592,128] + bias
//   K layout: k in [0,2304): spline (i=k>>3, c=k&7, uniform cubic B-spline
//             closed form); k in [2304,2592): silu(x_i); k in [2592,2624): pad.
// R9: persistent grid (296 CTAs, grid-stride over 481 M-tiles) + software-
//     pipelined builder (input LDG issued BEFORE compute, spline math after).
// ============================================================================

#define N_TOTAL   61504
#define K_TOTAL   2592
#define K_PAD     2624                 // 41 * 64
#define FILTERS   128
#define BM        128
#define NMT       481                  // M tiles
#define NKT       41
#define NSPLINE   36                   // tiles 0..35 cover k < 2304 exactly
#define GRID_P    296                  // persistent CTAs (2 per SM on 148 SMs)

#define ASTB       144                 // A row stride (bytes)
#define A_STAGE_B  (128 * ASTB)        // 18432
#define W_STAGE_B  16384               // 64k * 128o * 2B (frag-ordered)
#define SMEM_W_OFF (2 * A_STAGE_B)     // 36864
#define SMEM_TOTAL (2 * A_STAGE_B + 2 * W_STAGE_B)   // 69632 B

// W in m16n8k16 B-fragment word order per 64-k tile (4096 words):
//   word = ks*1024 + ob*64 + lane*2 + r
//   halfs: k = kt*64 + ks*16 + 2*(lane&3) + 8*r + hh,  o = ob*8 + (lane>>2)
__device__ __half g_Wh[K_PAD * FILTERS];

// ---------------------------------------------------------------- helpers --
__device__ __forceinline__ uint32_t pack2(float a, float b) {
    __half2 h = __floats2half2_rn(a, b);
    return *reinterpret_cast<uint32_t*>(&h);
}
__device__ __forceinline__ void sts16(uint32_t addr, uint32_t a, uint32_t b,
                                      uint32_t c, uint32_t d) {
    asm volatile("st.shared.v4.b32 [%0], {%1,%2,%3,%4};"
                 :: "r"(addr), "r"(a), "r"(b), "r"(c), "r"(d) : "memory");
}
__device__ __forceinline__ void lds_v2(uint32_t addr, uint32_t& a, uint32_t& b) {
    asm volatile("ld.shared.v2.b32 {%0,%1}, [%2];" : "=r"(a), "=r"(b) : "r"(addr));
}
__device__ __forceinline__ void ldsm4(uint32_t addr, uint32_t* r) {
    asm volatile("ldmatrix.sync.aligned.m8n8.x4.shared.b16 {%0,%1,%2,%3}, [%4];"
                 : "=r"(r[0]), "=r"(r[1]), "=r"(r[2]), "=r"(r[3]) : "r"(addr));
}
__device__ __forceinline__ void mma16(float* d, const uint32_t* a,
                                      uint32_t b0, uint32_t b1) {
    asm volatile(
        "mma.sync.aligned.m16n8k16.row.col.f32.f16.f16.f32 "
        "{%0,%1,%2,%3}, {%4,%5,%6,%7}, {%8,%9}, {%0,%1,%2,%3};"
        : "+f"(d[0]), "+f"(d[1]), "+f"(d[2]), "+f"(d[3])
        : "r"(a[0]), "r"(a[1]), "r"(a[2]), "r"(a[3]), "r"(b0), "r"(b1));
}
__device__ __forceinline__ void cpasync16(uint32_t saddr, const void* gptr) {
    asm volatile("cp.async.cg.shared.global [%0], [%1], 16;"
                 :: "r"(saddr), "l"(__cvta_generic_to_global(gptr)) : "memory");
}

// --------------------------------------------------------- weight fuse -----
__global__ void fuse_weights(const float* __restrict__ sk,   // [288,8,128]
                             const float* __restrict__ sc) { // [288,128]
    int w = blockIdx.x * 256 + threadIdx.x;                  // uint32 words
    if (w >= K_PAD * FILTERS / 2) return;
    int kt   = w >> 12;                 // 4096 words per 64-k tile
    int rem  = w & 4095;
    int ks   = rem >> 10;
    int ob   = (rem >> 6) & 15;
    int l    = (rem >> 1) & 31;
    int r    = rem & 1;
    int o    = ob * 8 + (l >> 2);
    int kb   = kt * 64 + ks * 16 + 2 * (l & 3) + 8 * r;
    float v[2];
#pragma unroll
    for (int hh = 0; hh < 2; ++hh) {
        int k = kb + hh;
        if (k < 2304) {
            int i = k >> 3;
            v[hh] = sk[k * 128 + o] * sc[i * 128 + o];
        } else if (k < 2592) {
            v[hh] = sc[(k - 2304) * 128 + o];
        } else {
            v[hh] = 0.f;                // pad
        }
    }
    ((uint32_t*)g_Wh)[w] = pack2(v[0], v[1]);
}

// ------------------------------------------------------------ A builder ----
// Spline prefetch: the 4 input channels this thread-half needs for tile kt.
__device__ __forceinline__ float4 prefetch_x(int kt, int bh,
                                             const float* __restrict__ rowbase) {
    int i0  = kt * 8 + bh * 4;
    int di  = i0 / 96;
    int rem = i0 - di * 96;
    int dj  = rem >> 5;
    int c0  = rem & 31;
    return *reinterpret_cast<const float4*>(rowbase + (di * 64 + dj) * 32 + c0);
}

// Build HALF of one row's 64-k slice. Spline tiles consume prefetched xv;
// silu tiles load inline (L1-hot by then).
__device__ __forceinline__ void build_from(int kt, int bh, float4 xv, uint32_t dst,
                                           const float* __restrict__ rowbase) {
    if (kt < NSPLINE) {
        float xs[4] = {xv.x, xv.y, xv.z, xv.w};
#pragma unroll
        for (int g = 0; g < 4; ++g) {
            float x  = xs[g];
            float tp = (x + 1.0f) * 2.5f;            // uniform grid, h = 0.4
            int j = (int)floorf(tp);
            j = max(0, min(4, j));
            float u  = tp - (float)j;
            float um = 1.0f - u;
            float u2 = u * u, u3 = u2 * u;
            float b0 = um * um * um * (1.0f / 6.0f);
            float b1 = (3.0f * u3 - 6.0f * u2 + 4.0f) * (1.0f / 6.0f);
            float b2 = (-3.0f * u3 + 3.0f * u2 + 3.0f * u + 1.0f) * (1.0f / 6.0f);
            float b3 = u3 * (1.0f / 6.0f);
            float f[8];
#pragma unroll
            for (int z = 0; z < 8; ++z) f[z] = 0.f;
            f[j]     = b0;
            f[j + 1] = b1;
            f[j + 2] = b2;
            f[j + 3] = b3;
            sts16(dst + g * 16,
                  pack2(f[0], f[1]), pack2(f[2], f[3]),
                  pack2(f[4], f[5]), pack2(f[6], f[7]));
        }
    } else {
        int ib = (kt - NSPLINE) * 2 + bh;            // 32-channel block
        if (ib < 9) {
            int di = ib / 3;
            int dj = ib - di * 3;
            const float* src = rowbase + (di * 64 + dj) * 32;
#pragma unroll
            for (int q = 0; q < 4; ++q) {
                float4 x0 = *reinterpret_cast<const float4*>(src + q * 8);
                float4 x1 = *reinterpret_cast<const float4*>(src + q * 8 + 4);
                float f[8] = {x0.x, x0.y, x0.z, x0.w, x1.x, x1.y, x1.z, x1.w};
                uint32_t p[4];
#pragma unroll
                for (int z = 0; z < 4; ++z) {
                    float a = f[2 * z],     sa = a / (1.0f + __expf(-a));
                    float b = f[2 * z + 1], sb = b / (1.0f + __expf(-b));
                    p[z] = pack2(sa, sb);
                }
                sts16(dst + q * 16, p[0], p[1], p[2], p[3]);
            }
        } else {
#pragma unroll
            for (int q = 0; q < 4; ++q)
                sts16(dst + q * 16, 0u, 0u, 0u, 0u);
        }
    }
}

// -------------------------------------------------------------- main -------
__global__ __launch_bounds__(256, 2)
void kan_mma_kernel(const float* __restrict__ input,   // [16,64,64,32]
                    const float* __restrict__ bias,    // [128]
                    float* __restrict__ out) {         // [61504,128]
    extern __shared__ char smem[];
    const uint32_t sb = (uint32_t)__cvta_generic_to_shared(smem);
    const uint32_t Ab = sb;
    const uint32_t Wb = sb + SMEM_W_OFF;

    const int tid = threadIdx.x;
    const int l   = tid & 31;
    const int wid = tid >> 5;
    const int wm  = wid >> 1;          // 0..3 : M warp row (32 rows)
    const int wn  = wid & 1;           // 0..1 : N warp col (64 cols)

    const int br = tid & 127;          // builder: row
    const int bh = tid >> 7;           // builder: k-half
    const uint32_t adst0 = Ab + (uint32_t)br * ASTB + (uint32_t)bh * 64;

    // ldmatrix / frag address pieces (fixed per thread)
    const uint32_t arow_sel  = (uint32_t)(wm * 32 + (l & 7) + ((l >> 3) & 1) * 8);
    const uint32_t acol_off  = (uint32_t)((l >> 4) * 16);
    const uint32_t wfrag_off = (uint32_t)(l * 8);

    const int ob = wn * 64 + (l & 3) * 2;   // base output col for this lane

    // -------- persistent loop over M tiles --------
    for (int mt = blockIdx.x; mt < NMT; mt += GRID_P) {
        int n = mt * BM + br;
        if (n >= N_TOTAL) n = N_TOTAL - 1;
        int bb = n / 3844;                  // 62*62
        int rr = n - bb * 3844;
        int yy = rr / 62;
        int xx = rr - yy * 62;
        const float* rowbase = input + ((bb * 64 + yy) * 64 + xx) * 32;

        // accumulators initialized with bias
        float acc[2][8][4];
#pragma unroll
        for (int nf = 0; nf < 8; ++nf) {
            float b0 = bias[ob + nf * 8];
            float b1 = bias[ob + nf * 8 + 1];
#pragma unroll
            for (int mf = 0; mf < 2; ++mf) {
                acc[mf][nf][0] = b0;
                acc[mf][nf][1] = b1;
                acc[mf][nf][2] = b0;
                acc[mf][nf][3] = b1;
            }
        }

        // ---- prologue: stage 0 ----
        {
            const char* wsrc = (const char*)g_Wh;
#pragma unroll
            for (int v = 0; v < 4; ++v)
                cpasync16(Wb + v * 4096 + tid * 16, wsrc + v * 4096 + tid * 16);
            asm volatile("cp.async.commit_group;" ::: "memory");
            float4 x0 = prefetch_x(0, bh, rowbase);
            build_from(0, bh, x0, adst0, rowbase);
            asm volatile("cp.async.wait_group 0;" ::: "memory");
        }
        __syncthreads();

        for (int kt = 0; kt < NKT; ++kt) {
            const int s = kt & 1;

            // ---- issue next-tile W cp.async and input LDG BEFORE compute ----
            float4 xn = make_float4(0.f, 0.f, 0.f, 0.f);
            if (kt + 1 < NKT) {
                const char* wsrc = (const char*)g_Wh + (size_t)(kt + 1) * W_STAGE_B;
                const uint32_t wdst = Wb + (s ^ 1) * W_STAGE_B;
#pragma unroll
                for (int v = 0; v < 4; ++v)
                    cpasync16(wdst + v * 4096 + tid * 16,
                              wsrc + v * 4096 + tid * 16);
                asm volatile("cp.async.commit_group;" ::: "memory");
                if (kt + 1 < NSPLINE)
                    xn = prefetch_x(kt + 1, bh, rowbase);   // hidden under compute
            }

            // ---- compute current tile: warp 32(M) x 64(N), k=64 (4 x k16) ----
            const uint32_t As = Ab + s * A_STAGE_B;
            const uint32_t Ws = Wb + s * W_STAGE_B;
#pragma unroll
            for (int ks = 0; ks < 4; ++ks) {
                uint32_t a[2][4];
#pragma unroll
                for (int mf = 0; mf < 2; ++mf)
                    ldsm4(As + (arow_sel + mf * 16) * ASTB + ks * 32 + acol_off,
                          a[mf]);
#pragma unroll
                for (int nf = 0; nf < 8; ++nf) {
                    uint32_t b0, b1;
                    lds_v2(Ws + ks * 4096 + (wn * 8 + nf) * 256 + wfrag_off, b0, b1);
#pragma unroll
                    for (int mf = 0; mf < 2; ++mf)
                        mma16(acc[mf][nf], a[mf], b0, b1);
                }
            }

            // ---- builder math + STS for next tile (after compute) ----
            if (kt + 1 < NKT)
                build_from(kt + 1, bh, xn, adst0 + (s ^ 1) * A_STAGE_B, rowbase);

            asm volatile("cp.async.wait_group 0;" ::: "memory");
            __syncthreads();
        }

        // ---- epilogue: direct float2 stores (bias already folded) ----
#pragma unroll
        for (int mf = 0; mf < 2; ++mf) {
            int r0 = mt * BM + wm * 32 + mf * 16 + (l >> 2);
#pragma unroll
            for (int nf = 0; nf < 8; ++nf) {
                int o = ob + nf * 8;
                if (r0 < N_TOTAL) {
                    float2 v = make_float2(acc[mf][nf][0], acc[mf][nf][1]);
                    *reinterpret_cast<float2*>(out + (size_t)r0 * FILTERS + o) = v;
                }
                if (r0 + 8 < N_TOTAL) {
                    float2 v = make_float2(acc[mf][nf][2], acc[mf][nf][3]);
                    *reinterpret_cast<float2*>(out + (size_t)(r0 + 8) * FILTERS + o) = v;
                }
            }
        }
        // no extra barrier needed: the k-loop's final __syncthreads ordered all
        // smem reads; epilogue touches only registers + gmem.
    }
}

// ------------------------------------------------------------- launcher ----
extern "C" void kernel_launch(void* const* d_in, const int* in_sizes, int n_in,
                              void* d_out, int out_size) {
    const float* input = (const float*)d_in[0];   // (16,64,64,32)
    const float* sk    = (const float*)d_in[1];   // (288,8,128)
    const float* sc    = (const float*)d_in[2];   // (288,128)
    const float* bias  = (const float*)d_in[3];   // (128,)
    float* out = (float*)d_out;
    (void)in_sizes; (void)n_in; (void)out_size;

    static bool attr_done = false;
    if (!attr_done) {
        cudaFuncSetAttribute(kan_mma_kernel,
                             cudaFuncAttributeMaxDynamicSharedMemorySize, SMEM_TOTAL);
        attr_done = true;
    }

    int wwords = K_PAD * FILTERS / 2;
    fuse_weights<<<(wwords + 255) / 256, 256>>>(sk, sc);

    kan_mma_kernel<<<GRID_P, 256, SMEM_TOTAL>>>(input, bias, out);
}

// round 10
// speedup vs baseline: 1.5856x; 1.5856x over previous
#include <cuda_runtime.h>
#include <cuda_fp16.h>
#include <math.h>
#include <stdint.h>

// ============================================================================
// ConvolutionKAN as mma.sync fp16 GEMM (sm_100-safe, fp32 accumulate):
//   out[61504,128] = A[61504,2592] @ W[2592,128] + bias
//   K layout: k in [0,2304): spline (i=k>>3, c=k&7, uniform cubic B-spline
//             closed form); k in [2304,2592): silu(x_i).
// R10: BM=64 (961 CTAs, exact fit), warp tile 16x64, 32 acc/thread ->
//      3 CTAs/SM (24 warps) for latency hiding + fine dynamic scheduling.
// ============================================================================

#define N_TOTAL   61504
#define K_TOTAL   2592
#define FILTERS   128
#define BM        64
#define NKT       81                   // 2592 / 32
#define NSPLINE   72                   // tiles 0..71: spline, 72..80: silu

#define ASTB       80                  // A row stride (bytes), conflict-free
#define A_STAGE_B  (BM * ASTB)         // 5120
#define W_STAGE_B  8192                // 32k * 128o * 2B (frag-ordered)
#define SMEM_W_OFF (2 * A_STAGE_B)     // 10240
#define SMEM_TOTAL (2 * A_STAGE_B + 2 * W_STAGE_B)   // 26624 B

// W in m16n8k16 B-fragment word order per 32-k tile (2048 words):
//   word = ks*1024 + ob*64 + lane*2 + r
//   halfs: k = kt*32 + ks*16 + 2*(lane&3) + 8*r + hh,  o = ob*8 + (lane>>2)
__device__ __half g_Wh[K_TOTAL * FILTERS];

// ---------------------------------------------------------------- helpers --
__device__ __forceinline__ uint32_t pack2(float a, float b) {
    __half2 h = __floats2half2_rn(a, b);
    return *reinterpret_cast<uint32_t*>(&h);
}
__device__ __forceinline__ void sts16(uint32_t addr, uint32_t a, uint32_t b,
                                      uint32_t c, uint32_t d) {
    asm volatile("st.shared.v4.b32 [%0], {%1,%2,%3,%4};"
                 :: "r"(addr), "r"(a), "r"(b), "r"(c), "r"(d) : "memory");
}
__device__ __forceinline__ void lds_v2(uint32_t addr, uint32_t& a, uint32_t& b) {
    asm volatile("ld.shared.v2.b32 {%0,%1}, [%2];" : "=r"(a), "=r"(b) : "r"(addr));
}
__device__ __forceinline__ void ldsm4(uint32_t addr, uint32_t* r) {
    asm volatile("ldmatrix.sync.aligned.m8n8.x4.shared.b16 {%0,%1,%2,%3}, [%4];"
                 : "=r"(r[0]), "=r"(r[1]), "=r"(r[2]), "=r"(r[3]) : "r"(addr));
}
__device__ __forceinline__ void mma16(float* d, const uint32_t* a,
                                      uint32_t b0, uint32_t b1) {
    asm volatile(
        "mma.sync.aligned.m16n8k16.row.col.f32.f16.f16.f32 "
        "{%0,%1,%2,%3}, {%4,%5,%6,%7}, {%8,%9}, {%0,%1,%2,%3};"
        : "+f"(d[0]), "+f"(d[1]), "+f"(d[2]), "+f"(d[3])
        : "r"(a[0]), "r"(a[1]), "r"(a[2]), "r"(a[3]), "r"(b0), "r"(b1));
}
__device__ __forceinline__ void cpasync16(uint32_t saddr, const void* gptr) {
    asm volatile("cp.async.cg.shared.global [%0], [%1], 16;"
                 :: "r"(saddr), "l"(__cvta_generic_to_global(gptr)) : "memory");
}

// --------------------------------------------------------- weight fuse -----
__global__ void fuse_weights(const float* __restrict__ sk,   // [288,8,128]
                             const float* __restrict__ sc) { // [288,128]
    int w = blockIdx.x * 256 + threadIdx.x;                  // uint32 words
    if (w >= K_TOTAL * FILTERS / 2) return;
    int kt   = w >> 11;                 // 2048 words per 32-k tile
    int rem  = w & 2047;
    int ks   = rem >> 10;
    int ob   = (rem >> 6) & 15;
    int l    = (rem >> 1) & 31;
    int r    = rem & 1;
    int o    = ob * 8 + (l >> 2);
    int kb   = kt * 32 + ks * 16 + 2 * (l & 3) + 8 * r;
    float v[2];
#pragma unroll
    for (int hh = 0; hh < 2; ++hh) {
        int k = kb + hh;
        if (k < 2304) {
            int i = k >> 3;
            v[hh] = sk[k * 128 + o] * sc[i * 128 + o];
        } else {
            v[hh] = sc[(k - 2304) * 128 + o];
        }
    }
    ((uint32_t*)g_Wh)[w] = pack2(v[0], v[1]);
}

// ------------------------------------------------------------ A builder ----
// Thread (row = tid>>2, q = tid&3) builds 8 halfs (16 B) of its row:
//   spline tile kt: channel i = kt*4 + q -> 8 basis values
//   silu tile:      channels 8q..8q+7 of 32-block (kt - 72)
__device__ __forceinline__ float prefetch_x(int kt, int q,
                                            const float* __restrict__ rowbase) {
    int i  = kt * 4 + q;
    int di = i / 96;
    int rm = i - di * 96;
    return rowbase[(di * 64 + (rm >> 5)) * 32 + (rm & 31)];
}

__device__ __forceinline__ void build_from(int kt, int q, float x, uint32_t dst,
                                           const float* __restrict__ rowbase) {
    if (kt < NSPLINE) {
        float tp = (x + 1.0f) * 2.5f;                // uniform grid, h = 0.4
        int j = (int)floorf(tp);
        j = max(0, min(4, j));
        float u  = tp - (float)j;
        float um = 1.0f - u;
        float u2 = u * u, u3 = u2 * u;
        float b0 = um * um * um * (1.0f / 6.0f);
        float b1 = (3.0f * u3 - 6.0f * u2 + 4.0f) * (1.0f / 6.0f);
        float b2 = (-3.0f * u3 + 3.0f * u2 + 3.0f * u + 1.0f) * (1.0f / 6.0f);
        float b3 = u3 * (1.0f / 6.0f);
        float f[8];
#pragma unroll
        for (int z = 0; z < 8; ++z) f[z] = 0.f;
        f[j]     = b0;
        f[j + 1] = b1;
        f[j + 2] = b2;
        f[j + 3] = b3;
        sts16(dst, pack2(f[0], f[1]), pack2(f[2], f[3]),
                   pack2(f[4], f[5]), pack2(f[6], f[7]));
    } else {
        int ib = kt - NSPLINE;                       // 32-channel block
        int di = ib / 3;
        int dj = ib - di * 3;
        const float* src = rowbase + (di * 64 + dj) * 32 + q * 8;
        float4 x0 = *reinterpret_cast<const float4*>(src);
        float4 x1 = *reinterpret_cast<const float4*>(src + 4);
        float f[8] = {x0.x, x0.y, x0.z, x0.w, x1.x, x1.y, x1.z, x1.w};
        uint32_t p[4];
#pragma unroll
        for (int z = 0; z < 4; ++z) {
            float a = f[2 * z],     sa = a / (1.0f + __expf(-a));
            float b = f[2 * z + 1], sb = b / (1.0f + __expf(-b));
            p[z] = pack2(sa, sb);
        }
        sts16(dst, p[0], p[1], p[2], p[3]);
    }
}

// -------------------------------------------------------------- main -------
__global__ __launch_bounds__(256, 3)
void kan_mma_kernel(const float* __restrict__ input,   // [16,64,64,32]
                    const float* __restrict__ bias,    // [128]
                    float* __restrict__ out) {         // [61504,128]
    extern __shared__ char smem[];
    const uint32_t sb = (uint32_t)__cvta_generic_to_shared(smem);
    const uint32_t Ab = sb;
    const uint32_t Wb = sb + SMEM_W_OFF;

    const int tid = threadIdx.x;
    const int l   = tid & 31;
    const int wid = tid >> 5;
    const int wm  = wid >> 1;          // 0..3 : M warp row (16 rows)
    const int wn  = wid & 1;           // 0..1 : N warp col (64 cols)

    // builder role: row = tid>>2, k-quarter q = tid&3
    const int brow = tid >> 2;
    const int bq   = tid & 3;
    const uint32_t adst0 = Ab + (uint32_t)brow * ASTB + (uint32_t)bq * 16;

    // this CTA's 64 rows: n = blockIdx.x*64 + brow  (exact fit, no clamp)
    {
        // nothing: computed below
    }
    int n  = blockIdx.x * BM + brow;
    int bb = n / 3844;                  // 62*62
    int rr = n - bb * 3844;
    int yy = rr / 62;
    int xx = rr - yy * 62;
    const float* rowbase = input + ((bb * 64 + yy) * 64 + xx) * 32;

    // fragment address pieces (fixed per thread)
    const uint32_t aaddr0    = (uint32_t)((wm * 16 + (l & 15)) * ASTB + (l >> 4) * 16);
    const uint32_t wfrag_off = (uint32_t)(l * 8);
    const int      ob        = wn * 64 + (l & 3) * 2;

    // accumulators initialized with bias
    float acc[8][4];
#pragma unroll
    for (int nf = 0; nf < 8; ++nf) {
        float b0 = bias[ob + nf * 8];
        float b1 = bias[ob + nf * 8 + 1];
        acc[nf][0] = b0;
        acc[nf][1] = b1;
        acc[nf][2] = b0;
        acc[nf][3] = b1;
    }

    // ---- prologue: stage 0 ----
    {
        const char* wsrc = (const char*)g_Wh;
#pragma unroll
        for (int v = 0; v < 2; ++v)
            cpasync16(Wb + v * 4096 + tid * 16, wsrc + v * 4096 + tid * 16);
        asm volatile("cp.async.commit_group;" ::: "memory");
        float x0 = prefetch_x(0, bq, rowbase);
        build_from(0, bq, x0, adst0, rowbase);
        asm volatile("cp.async.wait_group 0;" ::: "memory");
    }
    __syncthreads();

    for (int kt = 0; kt < NKT; ++kt) {
        const int s = kt & 1;

        // ---- stage next tile: W cp.async + input LDG before compute ----
        float xn = 0.f;
        if (kt + 1 < NKT) {
            const char* wsrc = (const char*)g_Wh + (size_t)(kt + 1) * W_STAGE_B;
            const uint32_t wdst = Wb + (s ^ 1) * W_STAGE_B;
#pragma unroll
            for (int v = 0; v < 2; ++v)
                cpasync16(wdst + v * 4096 + tid * 16, wsrc + v * 4096 + tid * 16);
            asm volatile("cp.async.commit_group;" ::: "memory");
            if (kt + 1 < NSPLINE)
                xn = prefetch_x(kt + 1, bq, rowbase);   // latency hides here
        }

        // ---- compute current tile: warp 16(M) x 64(N), k=32 (2 x k16) ----
        const uint32_t As = Ab + s * A_STAGE_B;
        const uint32_t Ws = Wb + s * W_STAGE_B;
#pragma unroll
        for (int ks = 0; ks < 2; ++ks) {
            uint32_t a[4];
            ldsm4(As + aaddr0 + ks * 32, a);
#pragma unroll
            for (int nf = 0; nf < 8; ++nf) {
                uint32_t b0, b1;
                lds_v2(Ws + ks * 4096 + (wn * 8 + nf) * 256 + wfrag_off, b0, b1);
                mma16(acc[nf], a, b0, b1);
            }
        }

        // ---- builder math + STS for next tile ----
        if (kt + 1 < NKT)
            build_from(kt + 1, bq, xn, adst0 + (s ^ 1) * A_STAGE_B, rowbase);

        asm volatile("cp.async.wait_group 0;" ::: "memory");
        __syncthreads();
    }

    // ---- epilogue: direct float2 stores (bias folded; exact fit, no guards) --
    const int r0 = blockIdx.x * BM + wm * 16 + (l >> 2);
#pragma unroll
    for (int nf = 0; nf < 8; ++nf) {
        int o = ob + nf * 8;
        *reinterpret_cast<float2*>(out + (size_t)r0 * FILTERS + o) =
            make_float2(acc[nf][0], acc[nf][1]);
        *reinterpret_cast<float2*>(out + (size_t)(r0 + 8) * FILTERS + o) =
            make_float2(acc[nf][2], acc[nf][3]);
    }
}

// ------------------------------------------------------------- launcher ----
extern "C" void kernel_launch(void* const* d_in, const int* in_sizes, int n_in,
                              void* d_out, int out_size) {
    const float* input = (const float*)d_in[0];   // (16,64,64,32)
    const float* sk    = (const float*)d_in[1];   // (288,8,128)
    const float* sc    = (const float*)d_in[2];   // (288,128)
    const float* bias  = (const float*)d_in[3];   // (128,)
    float* out = (float*)d_out;
    (void)in_sizes; (void)n_in; (void)out_size;

    static bool attr_done = false;
    if (!attr_done) {
        cudaFuncSetAttribute(kan_mma_kernel,
                             cudaFuncAttributeMaxDynamicSharedMemorySize, SMEM_TOTAL);
        attr_done = true;
    }

    int wwords = K_TOTAL * FILTERS / 2;
    fuse_weights<<<(wwords + 255) / 256, 256>>>(sk, sc);

    int blocks = N_TOTAL / BM;          // 961, exact
    kan_mma_kernel<<<blocks, 256, SMEM_TOTAL>>>(input, bias, out);
}

// round 11
// speedup vs baseline: 1.5933x; 1.0048x over previous
#include <cuda_runtime.h>
#include <cuda_fp16.h>
#include <math.h>
#include <stdint.h>

// ============================================================================
// ConvolutionKAN as mma.sync fp16 GEMM (sm_100-safe, fp32 accumulate):
//   out[61504,128] = A[61504,2592] @ W[2592,128] + bias
//   K layout: k in [0,2304): spline (i=k>>3, c=k&7, uniform cubic B-spline
//             closed form); k in [2304,2592): silu(x_i).
// R11: TRUE async W pipeline — 3-stage W buffer, cp.async issued 2 tiles
//      ahead, wait_group 1 (one group always in flight). Removes the full
//      L2 round-trip that sat on every tile's critical path since R7.
// ============================================================================

#define N_TOTAL   61504
#define K_TOTAL   2592
#define FILTERS   128
#define BM        64
#define NKT       81                   // 2592 / 32
#define NSPLINE   72                   // tiles 0..71: spline, 72..80: silu

#define ASTB       80                  // A row stride (bytes), conflict-free
#define A_STAGE_B  (BM * ASTB)         // 5120
#define W_STAGE_B  8192                // 32k * 128o * 2B (frag-ordered)
#define SMEM_W_OFF (2 * A_STAGE_B)     // 10240
#define SMEM_TOTAL (2 * A_STAGE_B + 3 * W_STAGE_B)   // 34816 B

// W in m16n8k16 B-fragment word order per 32-k tile (2048 words):
//   word = ks*1024 + ob*64 + lane*2 + r
//   halfs: k = kt*32 + ks*16 + 2*(lane&3) + 8*r + hh,  o = ob*8 + (lane>>2)
__device__ __half g_Wh[K_TOTAL * FILTERS];

// ---------------------------------------------------------------- helpers --
__device__ __forceinline__ uint32_t pack2(float a, float b) {
    __half2 h = __floats2half2_rn(a, b);
    return *reinterpret_cast<uint32_t*>(&h);
}
__device__ __forceinline__ void sts16(uint32_t addr, uint32_t a, uint32_t b,
                                      uint32_t c, uint32_t d) {
    asm volatile("st.shared.v4.b32 [%0], {%1,%2,%3,%4};"
                 :: "r"(addr), "r"(a), "r"(b), "r"(c), "r"(d) : "memory");
}
__device__ __forceinline__ void lds_v2(uint32_t addr, uint32_t& a, uint32_t& b) {
    asm volatile("ld.shared.v2.b32 {%0,%1}, [%2];" : "=r"(a), "=r"(b) : "r"(addr));
}
__device__ __forceinline__ void ldsm4(uint32_t addr, uint32_t* r) {
    asm volatile("ldmatrix.sync.aligned.m8n8.x4.shared.b16 {%0,%1,%2,%3}, [%4];"
                 : "=r"(r[0]), "=r"(r[1]), "=r"(r[2]), "=r"(r[3]) : "r"(addr));
}
__device__ __forceinline__ void mma16(float* d, const uint32_t* a,
                                      uint32_t b0, uint32_t b1) {
    asm volatile(
        "mma.sync.aligned.m16n8k16.row.col.f32.f16.f16.f32 "
        "{%0,%1,%2,%3}, {%4,%5,%6,%7}, {%8,%9}, {%0,%1,%2,%3};"
        : "+f"(d[0]), "+f"(d[1]), "+f"(d[2]), "+f"(d[3])
        : "r"(a[0]), "r"(a[1]), "r"(a[2]), "r"(a[3]), "r"(b0), "r"(b1));
}
__device__ __forceinline__ void cpasync16(uint32_t saddr, const void* gptr) {
    asm volatile("cp.async.cg.shared.global [%0], [%1], 16;"
                 :: "r"(saddr), "l"(__cvta_generic_to_global(gptr)) : "memory");
}
#define CP_COMMIT()  asm volatile("cp.async.commit_group;" ::: "memory")
#define CP_WAIT1()   asm volatile("cp.async.wait_group 1;" ::: "memory")

// --------------------------------------------------------- weight fuse -----
__global__ void fuse_weights(const float* __restrict__ sk,   // [288,8,128]
                             const float* __restrict__ sc) { // [288,128]
    int w = blockIdx.x * 256 + threadIdx.x;                  // uint32 words
    if (w >= K_TOTAL * FILTERS / 2) return;
    int kt   = w >> 11;                 // 2048 words per 32-k tile
    int rem  = w & 2047;
    int ks   = rem >> 10;
    int ob   = (rem >> 6) & 15;
    int l    = (rem >> 1) & 31;
    int r    = rem & 1;
    int o    = ob * 8 + (l >> 2);
    int kb   = kt * 32 + ks * 16 + 2 * (l & 3) + 8 * r;
    float v[2];
#pragma unroll
    for (int hh = 0; hh < 2; ++hh) {
        int k = kb + hh;
        if (k < 2304) {
            int i = k >> 3;
            v[hh] = sk[k * 128 + o] * sc[i * 128 + o];
        } else {
            v[hh] = sc[(k - 2304) * 128 + o];
        }
    }
    ((uint32_t*)g_Wh)[w] = pack2(v[0], v[1]);
}

// ------------------------------------------------------------ A builder ----
// Thread (row = tid>>2, q = tid&3) builds 8 halfs (16 B) of its row.
__device__ __forceinline__ float prefetch_x(int kt, int q,
                                            const float* __restrict__ rowbase) {
    int i  = kt * 4 + q;
    int di = i / 96;
    int rm = i - di * 96;
    return rowbase[(di * 64 + (rm >> 5)) * 32 + (rm & 31)];
}

__device__ __forceinline__ void build_from(int kt, int q, float x, uint32_t dst,
                                           const float* __restrict__ rowbase) {
    if (kt < NSPLINE) {
        float tp = (x + 1.0f) * 2.5f;                // uniform grid, h = 0.4
        int j = (int)floorf(tp);
        j = max(0, min(4, j));
        float u  = tp - (float)j;
        float um = 1.0f - u;
        float u2 = u * u, u3 = u2 * u;
        float b0 = um * um * um * (1.0f / 6.0f);
        float b1 = (3.0f * u3 - 6.0f * u2 + 4.0f) * (1.0f / 6.0f);
        float b2 = (-3.0f * u3 + 3.0f * u2 + 3.0f * u + 1.0f) * (1.0f / 6.0f);
        float b3 = u3 * (1.0f / 6.0f);
        float f[8];
#pragma unroll
        for (int z = 0; z < 8; ++z) f[z] = 0.f;
        f[j]     = b0;
        f[j + 1] = b1;
        f[j + 2] = b2;
        f[j + 3] = b3;
        sts16(dst, pack2(f[0], f[1]), pack2(f[2], f[3]),
                   pack2(f[4], f[5]), pack2(f[6], f[7]));
    } else {
        int ib = kt - NSPLINE;                       // 32-channel block
        int di = ib / 3;
        int dj = ib - di * 3;
        const float* src = rowbase + (di * 64 + dj) * 32 + q * 8;
        float4 x0 = *reinterpret_cast<const float4*>(src);
        float4 x1 = *reinterpret_cast<const float4*>(src + 4);
        float f[8] = {x0.x, x0.y, x0.z, x0.w, x1.x, x1.y, x1.z, x1.w};
        uint32_t p[4];
#pragma unroll
        for (int z = 0; z < 4; ++z) {
            float a = f[2 * z],     sa = a / (1.0f + __expf(-a));
            float b = f[2 * z + 1], sb = b / (1.0f + __expf(-b));
            p[z] = pack2(sa, sb);
        }
        sts16(dst, p[0], p[1], p[2], p[3]);
    }
}

// -------------------------------------------------------------- main -------
__global__ __launch_bounds__(256, 3)
void kan_mma_kernel(const float* __restrict__ input,   // [16,64,64,32]
                    const float* __restrict__ bias,    // [128]
                    float* __restrict__ out) {         // [61504,128]
    extern __shared__ char smem[];
    const uint32_t sb = (uint32_t)__cvta_generic_to_shared(smem);
    const uint32_t Ab = sb;
    const uint32_t Wb = sb + SMEM_W_OFF;

    const int tid = threadIdx.x;
    const int l   = tid & 31;
    const int wid = tid >> 5;
    const int wm  = wid >> 1;          // 0..3 : M warp row (16 rows)
    const int wn  = wid & 1;           // 0..1 : N warp col (64 cols)

    // builder role: row = tid>>2, k-quarter q = tid&3
    const int brow = tid >> 2;
    const int bq   = tid & 3;
    const uint32_t adst0 = Ab + (uint32_t)brow * ASTB + (uint32_t)bq * 16;

    int n  = blockIdx.x * BM + brow;    // exact fit: 961 * 64 = 61504
    int bb = n / 3844;                  // 62*62
    int rr = n - bb * 3844;
    int yy = rr / 62;
    int xx = rr - yy * 62;
    const float* rowbase = input + ((bb * 64 + yy) * 64 + xx) * 32;

    // fragment address pieces (fixed per thread)
    const uint32_t aaddr0    = (uint32_t)((wm * 16 + (l & 15)) * ASTB + (l >> 4) * 16);
    const uint32_t wfrag_off = (uint32_t)(l * 8);
    const int      ob        = wn * 64 + (l & 3) * 2;

    // accumulators initialized with bias
    float acc[8][4];
#pragma unroll
    for (int nf = 0; nf < 8; ++nf) {
        float b0 = bias[ob + nf * 8];
        float b1 = bias[ob + nf * 8 + 1];
        acc[nf][0] = b0;
        acc[nf][1] = b1;
        acc[nf][2] = b0;
        acc[nf][3] = b1;
    }

    // ---- prologue: W groups for tiles 0 and 1; build A tile 0 ----
    {
        const char* wsrc = (const char*)g_Wh;
#pragma unroll
        for (int v = 0; v < 2; ++v)
            cpasync16(Wb + v * 4096 + tid * 16, wsrc + v * 4096 + tid * 16);
        CP_COMMIT();                                   // group: tile 0
#pragma unroll
        for (int v = 0; v < 2; ++v)
            cpasync16(Wb + W_STAGE_B + v * 4096 + tid * 16,
                      wsrc + W_STAGE_B + v * 4096 + tid * 16);
        CP_COMMIT();                                   // group: tile 1
        float x0 = prefetch_x(0, bq, rowbase);
        build_from(0, bq, x0, adst0, rowbase);
        CP_WAIT1();                                    // tile 0 ready
    }
    __syncthreads();

    for (int kt = 0; kt < NKT; ++kt) {
        // ---- issue W cp.async for tile kt+2 (2 ahead) ----
        if (kt + 2 < NKT) {
            const char* wsrc = (const char*)g_Wh + (size_t)(kt + 2) * W_STAGE_B;
            const uint32_t wdst = Wb + ((kt + 2) % 3) * W_STAGE_B;
#pragma unroll
            for (int v = 0; v < 2; ++v)
                cpasync16(wdst + v * 4096 + tid * 16, wsrc + v * 4096 + tid * 16);
        }
        CP_COMMIT();   // always commit (possibly empty) -> uniform accounting

        // input prefetch for next tile's spline build (hidden under compute)
        float xn = 0.f;
        if (kt + 1 < NSPLINE)
            xn = prefetch_x(kt + 1, bq, rowbase);

        // ---- compute tile kt: warp 16(M) x 64(N), k=32 (2 x k16) ----
        const uint32_t As = Ab + (kt & 1) * A_STAGE_B;
        const uint32_t Ws = Wb + (kt % 3) * W_STAGE_B;
#pragma unroll
        for (int ks = 0; ks < 2; ++ks) {
            uint32_t a[4];
            ldsm4(As + aaddr0 + ks * 32, a);
#pragma unroll
            for (int nf = 0; nf < 8; ++nf) {
                uint32_t b0, b1;
                lds_v2(Ws + ks * 4096 + (wn * 8 + nf) * 256 + wfrag_off, b0, b1);
                mma16(acc[nf], a, b0, b1);
            }
        }

        // ---- builder math + STS for tile kt+1 ----
        if (kt + 1 < NKT)
            build_from(kt + 1, bq, xn, adst0 + ((kt + 1) & 1) * A_STAGE_B, rowbase);

        CP_WAIT1();        // tile kt+1's W group complete; kt+2 stays in flight
        __syncthreads();
    }

    // ---- epilogue: direct float2 stores (bias folded; exact fit) ----
    const int r0 = blockIdx.x * BM + wm * 16 + (l >> 2);
#pragma unroll
    for (int nf = 0; nf < 8; ++nf) {
        int o = ob + nf * 8;
        *reinterpret_cast<float2*>(out + (size_t)r0 * FILTERS + o) =
            make_float2(acc[nf][0], acc[nf][1]);
        *reinterpret_cast<float2*>(out + (size_t)(r0 + 8) * FILTERS + o) =
            make_float2(acc[nf][2], acc[nf][3]);
    }
}

// ------------------------------------------------------------- launcher ----
extern "C" void kernel_launch(void* const* d_in, const int* in_sizes, int n_in,
                              void* d_out, int out_size) {
    const float* input = (const float*)d_in[0];   // (16,64,64,32)
    const float* sk    = (const float*)d_in[1];   // (288,8,128)
    const float* sc    = (const float*)d_in[2];   // (288,128)
    const float* bias  = (const float*)d_in[3];   // (128,)
    float* out = (float*)d_out;
    (void)in_sizes; (void)n_in; (void)out_size;

    static bool attr_done = false;
    if (!attr_done) {
        cudaFuncSetAttribute(kan_mma_kernel,
                             cudaFuncAttributeMaxDynamicSharedMemorySize, SMEM_TOTAL);
        attr_done = true;
    }

    int wwords = K_TOTAL * FILTERS / 2;
    fuse_weights<<<(wwords + 255) / 256, 256>>>(sk, sc);

    int blocks = N_TOTAL / BM;          // 961, exact
    kan_mma_kernel<<<blocks, 256, SMEM_TOTAL>>>(input, bias, out);
}